// round 4
// baseline (speedup 1.0000x reference)
#include <cuda_runtime.h>
#include <cuda_bf16.h>

#define BB 512
#define CC 3
#define TT 16384
#define NBLOCKS 1024
#define NTHREADS 256

// Deterministic partial-sum scratch (no device-side allocation allowed).
__device__ float g_ce[NBLOCKS];
__device__ float g_sq[NBLOCKS];
__device__ int   g_fl[NBLOCKS];
__device__ unsigned int g_tick = 0;   // wraps back to 0 every launch -> replay-safe

__device__ __forceinline__ int argmax3(float x0, float x1, float x2) {
    // First-occurrence-of-max semantics (matches jnp.argmax): strict >.
    int idx = 0; float best = x0;
    if (x1 > best) { best = x1; idx = 1; }
    if (x2 > best) { idx = 2; }
    return idx;
}

__global__ void __launch_bounds__(NTHREADS)
ce_fused_kernel(const float* __restrict__ logits, const int* __restrict__ labels,
                float* __restrict__ out) {
    const int T8  = TT / 8;                    // 2048 chunks per row
    const int NCH = BB * T8;                   // 1,048,576 chunks

    float ce = 0.0f;
    float sq = 0.0f;
    int   fl = 0;

    const int stride = gridDim.x * blockDim.x;
    for (int ci = blockIdx.x * blockDim.x + threadIdx.x; ci < NCH; ci += stride) {
        const int t8 = ci & (T8 - 1);
        const int b  = ci >> 11;               // ci / 2048
        const int t  = t8 * 8;

        const float* p = logits + (long long)b * (CC * TT) + t;
        // 8 consecutive t per class row: 2 float4 each, issued front-batched.
        const float4 a0 = *reinterpret_cast<const float4*>(p);
        const float4 a1 = *reinterpret_cast<const float4*>(p + 4);
        const float4 b0 = *reinterpret_cast<const float4*>(p + TT);
        const float4 b1 = *reinterpret_cast<const float4*>(p + TT + 4);
        const float4 c0 = *reinterpret_cast<const float4*>(p + 2 * TT);
        const float4 c1 = *reinterpret_cast<const float4*>(p + 2 * TT + 4);

        const int4 q0 = *reinterpret_cast<const int4*>(labels + (long long)b * TT + t);
        const int4 q1 = *reinterpret_cast<const int4*>(labels + (long long)b * TT + t + 4);

        float xa[8] = { a0.x, a0.y, a0.z, a0.w, a1.x, a1.y, a1.z, a1.w };
        float xb[8] = { b0.x, b0.y, b0.z, b0.w, b1.x, b1.y, b1.z, b1.w };
        float xc[8] = { c0.x, c0.y, c0.z, c0.w, c1.x, c1.y, c1.z, c1.w };
        int  lab[8] = { q0.x, q0.y, q0.z, q0.w, q1.x, q1.y, q1.z, q1.w };

        // Boundary at t+8 (L1/L2 hits — neighbor thread's lines).
        const bool has_next = (t + 8 < TT);
        float n0 = 0.f, n1 = 0.f, n2 = 0.f;
        if (has_next) {
            n0 = p[8];
            n1 = p[TT + 8];
            n2 = p[2 * TT + 8];
        }

        int pr[9];
        #pragma unroll
        for (int j = 0; j < 8; j++) {
            const float x0 = xa[j], x1 = xb[j], x2 = xc[j];
            // sort3 via FMNMX; exp(hi-hi)=1 is free -> only 2 EX2 + 1 LG2.
            const float t0 = fminf(x0, x1), t1 = fmaxf(x0, x1);
            const float hi  = fmaxf(t1, x2);
            const float mid = fmaxf(t0, fminf(t1, x2));
            const float lo  = fminf(t0, x2);
            const float s   = 1.0f + __expf(mid - hi) + __expf(lo - hi);
            const float lse = hi + __logf(s);
            const int l = lab[j];
            const float xl = (l == 0) ? x0 : ((l == 1) ? x1 : x2);
            ce += lse - xl;
            pr[j] = argmax3(x0, x1, x2);
        }

        // smoothness: 7 in-register diffs per class + boundary
        #pragma unroll
        for (int j = 0; j < 7; j++) {
            const float d0 = xa[j + 1] - xa[j];
            const float d1 = xb[j + 1] - xb[j];
            const float d2 = xc[j + 1] - xc[j];
            sq += d0 * d0 + d1 * d1 + d2 * d2;
        }
        if (has_next) {
            const float d0 = n0 - xa[7];
            const float d1 = n1 - xb[7];
            const float d2 = n2 - xc[7];
            sq += d0 * d0 + d1 * d1 + d2 * d2;
            pr[8] = argmax3(n0, n1, n2);
        }

        // transitions: bad pair iff (prev,next) in {(0,2),(1,0),(2,1)} -> bits 2,3,7 of 0x8C
        const int npairs = has_next ? 8 : 7;
        #pragma unroll
        for (int j = 0; j < 8; j++) {
            if (j < npairs) {
                fl |= (0x8C >> (pr[j] * 3 + pr[j + 1])) & 1;
            }
        }
    }

    // Deterministic block-tree reduction into partials.
    __shared__ float sce[NTHREADS];
    __shared__ float ssq[NTHREADS];
    __shared__ int   sfl[NTHREADS];
    const int tid = threadIdx.x;
    sce[tid] = ce; ssq[tid] = sq; sfl[tid] = fl;
    __syncthreads();
    for (int s = NTHREADS / 2; s > 0; s >>= 1) {
        if (tid < s) {
            sce[tid] += sce[tid + s];
            ssq[tid] += ssq[tid + s];
            sfl[tid] |= sfl[tid + s];
        }
        __syncthreads();
    }

    __shared__ int is_last;
    if (tid == 0) {
        g_ce[blockIdx.x] = sce[0];
        g_sq[blockIdx.x] = ssq[0];
        g_fl[blockIdx.x] = sfl[0];
        __threadfence();
        // atomicInc wraps to 0 after NBLOCKS-1 -> counter is 0 again next launch.
        const unsigned int ticket = atomicInc(&g_tick, NBLOCKS - 1);
        is_last = (ticket == NBLOCKS - 1);
    }
    __syncthreads();

    if (is_last) {
        // Last block reduces the 1024 partials in a FIXED order -> deterministic.
        float fce = 0.f, fsq = 0.f; int ffl = 0;
        #pragma unroll
        for (int k = 0; k < NBLOCKS / NTHREADS; k++) {
            const int idx = tid + k * NTHREADS;
            fce += g_ce[idx];
            fsq += g_sq[idx];
            ffl |= g_fl[idx];
        }
        sce[tid] = fce; ssq[tid] = fsq; sfl[tid] = ffl;
        __syncthreads();
        for (int s = NTHREADS / 2; s > 0; s >>= 1) {
            if (tid < s) {
                sce[tid] += sce[tid + s];
                ssq[tid] += ssq[tid + s];
                sfl[tid] |= sfl[tid + s];
            }
            __syncthreads();
        }
        if (tid == 0) {
            const float ce_mean = sce[0] / (float)((long long)BB * TT);
            const float smooth  = 0.01f * (ssq[0] / (float)((long long)BB * CC * (TT - 1)));
            const float trans   = sfl[0] ? 0.1f : 0.0f;
            out[0] = ce_mean + smooth + trans;
        }
    }
}

extern "C" void kernel_launch(void* const* d_in, const int* in_sizes, int n_in,
                              void* d_out, int out_size) {
    // Identify inputs by element count, independent of metadata order.
    const long long N_LOGITS = (long long)BB * CC * TT;  // 25,165,824
    const float* logits = nullptr;
    const int*   labels = nullptr;
    for (int i = 0; i < n_in; i++) {
        if (in_sizes[i] == (int)N_LOGITS) logits = (const float*)d_in[i];
        else                              labels = (const int*)d_in[i];
    }
    float* out = (float*)d_out;

    ce_fused_kernel<<<NBLOCKS, NTHREADS>>>(logits, labels, out);
}